// round 2
// baseline (speedup 1.0000x reference)
#include <cuda_runtime.h>
#include <cstdint>

// Problem constants
#define CND   256                 // feature channels
#define VN    4096                // codebook size
#define NPTS  32768               // total points = 8 * 16^3
#define PB    4096                // points per batch (16^3)
#define A_ELEMS (NPTS * CND)      // 8,388,608 elements per quant output

// GEMM tiling
#define TM 128                    // points per block
#define TV 128                    // codewords per tile
#define KC 16                     // K-chunk
#define NKC (CND / KC)            // 16
#define NVT (VN / TV)             // 32
#define SX_STRIDE 132             // padded smem row stride (floats)
#define SW_STRIDE 132

#define NBLOCKS_VQ (NPTS / TM)    // 256
#define NBLOCKS_WR 128            // writer blocks (256 threads each)

// Scratch (device globals; no allocation allowed)
__device__ float  g_wsq[VN];
__device__ int    g_idx[NPTS];
__device__ double g_blocksum[NBLOCKS_WR];

// ---------------------------------------------------------------------------
// Kernel 0: per-codeword squared norms ||w_v||^2
// ---------------------------------------------------------------------------
__global__ void wsq_kernel(const float* __restrict__ W) {
    int v = blockIdx.x * blockDim.x + threadIdx.x;
    if (v < VN) {
        const float* row = W + (size_t)v * CND;
        float s = 0.f;
        #pragma unroll 8
        for (int c = 0; c < CND; c++) s = fmaf(row[c], row[c], s);
        g_wsq[v] = s;
    }
}

// ---------------------------------------------------------------------------
// Kernel 1: fused distance-GEMM + argmin.
// Each block: TM=128 points, loops over all V in TV=128 tiles.
// score(v) = ||w_v||^2 - 2 * x.w_v   (||x||^2 constant per point -> argmin-safe)
// ---------------------------------------------------------------------------
struct WPF { float4 a, b; };

__device__ __forceinline__ WPF load_w_chunk(const float* __restrict__ W,
                                            int v0, int k0, int tid) {
    WPF r;
    int i0 = tid, i1 = tid + 256;
    r.a = *reinterpret_cast<const float4*>(
        W + (size_t)(v0 + (i0 >> 2)) * CND + k0 + ((i0 & 3) << 2));
    r.b = *reinterpret_cast<const float4*>(
        W + (size_t)(v0 + (i1 >> 2)) * CND + k0 + ((i1 & 3) << 2));
    return r;
}

__device__ __forceinline__ void store_w_chunk(float* __restrict__ swb,
                                              const WPF& pf, int tid) {
    // transpose [v][k0..k0+15] -> sw[k][v]  (K-major for the GEMM microkernel)
    {
        int i0 = tid;
        int v = i0 >> 2, j = i0 & 3;
        float* d = swb + (4 * j) * SW_STRIDE + v;
        d[0]             = pf.a.x;
        d[SW_STRIDE]     = pf.a.y;
        d[2 * SW_STRIDE] = pf.a.z;
        d[3 * SW_STRIDE] = pf.a.w;
    }
    {
        int i1 = tid + 256;
        int v = i1 >> 2, j = i1 & 3;
        float* d = swb + (4 * j) * SW_STRIDE + v;
        d[0]             = pf.b.x;
        d[SW_STRIDE]     = pf.b.y;
        d[2 * SW_STRIDE] = pf.b.z;
        d[3 * SW_STRIDE] = pf.b.w;
    }
}

__global__ __launch_bounds__(256, 1)
void vq_kernel(const float* __restrict__ G, const float* __restrict__ W,
               float* __restrict__ out_idx) {
    extern __shared__ float smem[];
    float* sx   = smem;                        // [CND][SX_STRIDE]  (x tile, K-major)
    float* sw   = smem + CND * SX_STRIDE;      // 2 x [KC][SW_STRIDE] (W tile dbuf)
    float* swsq = sw + 2 * KC * SW_STRIDE;     // [TV]

    const int tid = threadIdx.x;
    const int tx  = tid & 15;                  // m-direction (points)
    const int ty  = tid >> 4;                  // v-direction (codewords)
    const int n0  = blockIdx.x * TM;
    const int b   = n0 / PB;
    const int p0  = n0 % PB;
    const float* Gb = G + (size_t)b * CND * PB + p0;

    // Stage the full x tile once: 256 rows x 128 contiguous floats (coalesced).
    for (int i = tid; i < CND * (TM / 4); i += 256) {
        int c  = i >> 5;                       // TM/4 == 32
        int m4 = i & 31;
        float4 v = *reinterpret_cast<const float4*>(Gb + (size_t)c * PB + m4 * 4);
        *reinterpret_cast<float4*>(sx + c * SX_STRIDE + m4 * 4) = v;
    }

    float best[8];
    int   bidx[8];
    #pragma unroll
    for (int i = 0; i < 8; i++) { best[i] = 3.4e38f; bidx[i] = 0; }

    __syncthreads();

    #pragma unroll 1
    for (int vt = 0; vt < NVT; vt++) {
        const int v0 = vt * TV;

        float acc[8][8];
        #pragma unroll
        for (int i = 0; i < 8; i++)
            #pragma unroll
            for (int j = 0; j < 8; j++) acc[i][j] = 0.f;

        if (tid < TV) swsq[tid] = g_wsq[v0 + tid];

        WPF pf = load_w_chunk(W, v0, 0, tid);
        store_w_chunk(sw, pf, tid);
        __syncthreads();

        int cur = 0;
        #pragma unroll 1
        for (int kc = 0; kc < NKC; kc++) {
            const bool has_next = (kc + 1 < NKC);
            if (has_next) pf = load_w_chunk(W, v0, (kc + 1) * KC, tid);

            const float* sxr0 = sx + kc * KC * SX_STRIDE + tx * 8;
            const float* swr0 = sw + cur * KC * SW_STRIDE + ty * 8;
            #pragma unroll
            for (int k = 0; k < KC; k++) {
                float a[8], bb[8];
                *reinterpret_cast<float4*>(&a[0]) =
                    *reinterpret_cast<const float4*>(sxr0 + k * SX_STRIDE);
                *reinterpret_cast<float4*>(&a[4]) =
                    *reinterpret_cast<const float4*>(sxr0 + k * SX_STRIDE + 4);
                *reinterpret_cast<float4*>(&bb[0]) =
                    *reinterpret_cast<const float4*>(swr0 + k * SW_STRIDE);
                *reinterpret_cast<float4*>(&bb[4]) =
                    *reinterpret_cast<const float4*>(swr0 + k * SW_STRIDE + 4);
                #pragma unroll
                for (int i = 0; i < 8; i++)
                    #pragma unroll
                    for (int j = 0; j < 8; j++)
                        acc[i][j] = fmaf(a[i], bb[j], acc[i][j]);
            }
            __syncthreads();
            if (has_next) {
                store_w_chunk(sw + (cur ^ 1) * KC * SW_STRIDE, pf, tid);
                cur ^= 1;
                __syncthreads();
            }
        }

        // Epilogue: score + running argmin. Strict '<' + ascending v order
        // ensures ties resolve to the smallest index (matches jnp.argmin).
        #pragma unroll
        for (int j = 0; j < 8; j++) {
            const int   vv = v0 + ty * 8 + j;
            const float ws = swsq[ty * 8 + j];
            #pragma unroll
            for (int i = 0; i < 8; i++) {
                float s = fmaf(-2.f, acc[i][j], ws);
                if (s < best[i]) { best[i] = s; bidx[i] = vv; }
            }
        }
        __syncthreads();   // protect swsq/sw before next tile rewrites them
    }

    // Cross-thread reduction: 16 ty-partials per point, in reused sw smem.
    float* rs = sw;                       // [16][TM] scores
    int*   ri = (int*)(sw + 16 * TM);     // [16][TM] indices
    #pragma unroll
    for (int i = 0; i < 8; i++) {
        rs[ty * TM + tx * 8 + i] = best[i];
        ri[ty * TM + tx * 8 + i] = bidx[i];
    }
    __syncthreads();
    if (tid < TM) {
        float bs = rs[tid];
        int   bi = ri[tid];
        #pragma unroll 1
        for (int t = 1; t < 16; t++) {
            float s  = rs[t * TM + tid];
            int   ii = ri[t * TM + tid];
            if (s < bs || (s == bs && ii < bi)) { bs = s; bi = ii; }
        }
        const int n = n0 + tid;
        g_idx[n]   = bi;
        out_idx[n] = (float)bi;
    }
}

// ---------------------------------------------------------------------------
// Kernel 2: scatter quant_feat / quant_feat_st + per-block fp64 MSE partials.
// Thread n handles one point across all 256 channels (writes coalesced over p).
// ---------------------------------------------------------------------------
__global__ __launch_bounds__(256)
void write_kernel(const float* __restrict__ G, const float* __restrict__ W,
                  float* __restrict__ out) {
    const int n = blockIdx.x * blockDim.x + threadIdx.x;
    const int b = n / PB;
    const int p = n % PB;
    const int idx = g_idx[n];
    const float* wrow = W + (size_t)idx * CND;
    const float* g    = G + (size_t)b * CND * PB + p;
    float* q1 = out + (size_t)b * CND * PB + p;
    float* q2 = q1 + (size_t)A_ELEMS;

    double sum = 0.0;
    #pragma unroll 4
    for (int c = 0; c < CND; c++) {
        float w  = __ldg(wrow + c);
        float gg = g[(size_t)c * PB];
        q1[(size_t)c * PB] = w;
        q2[(size_t)c * PB] = w;
        float d = gg - w;
        sum += (double)d * (double)d;
    }

    __shared__ double sred[256];
    sred[threadIdx.x] = sum;
    __syncthreads();
    for (int s = 128; s > 0; s >>= 1) {
        if (threadIdx.x < s) sred[threadIdx.x] += sred[threadIdx.x + s];
        __syncthreads();
    }
    if (threadIdx.x == 0) g_blocksum[blockIdx.x] = sred[0];
}

// ---------------------------------------------------------------------------
// Kernel 3: deterministic final sum -> quant_diff scalar
// ---------------------------------------------------------------------------
__global__ void final_kernel(float* __restrict__ out) {
    double s = 0.0;
    for (int i = 0; i < NBLOCKS_WR; i++) s += g_blocksum[i];
    out[2 * (size_t)A_ELEMS + NPTS] = (float)(s / ((double)NPTS * (double)CND));
}

// ---------------------------------------------------------------------------
// Launch. Output layout (float32, concatenated in reference return order):
//   [0, A)           quant_feat       (b, c, x, y, z)
//   [A, 2A)          quant_feat_st    (numerically identical to quant_feat)
//   [2A, 2A+NPTS)    enc_idx          (cast to float)
//   [2A+NPTS]        quant_diff
// ---------------------------------------------------------------------------
extern "C" void kernel_launch(void* const* d_in, const int* in_sizes, int n_in,
                              void* d_out, int out_size) {
    const float* G = (const float*)d_in[0];   // grid_feat [8,256,16,16,16]
    const float* W = (const float*)d_in[1];   // weight    [4096,256]
    float* out = (float*)d_out;

    const int smem_bytes = (CND * SX_STRIDE + 2 * KC * SW_STRIDE + TV) * 4;
    cudaFuncSetAttribute(vq_kernel, cudaFuncAttributeMaxDynamicSharedMemorySize,
                         smem_bytes);

    wsq_kernel<<<(VN + 255) / 256, 256>>>(W);
    vq_kernel<<<NBLOCKS_VQ, 256, smem_bytes>>>(G, W, out + 2 * (size_t)A_ELEMS);
    write_kernel<<<NBLOCKS_WR, 256>>>(G, W, out);
    final_kernel<<<1, 1>>>(out);
}

// round 5
// speedup vs baseline: 1.5671x; 1.5671x over previous
#include <cuda_runtime.h>
#include <cstdint>

#define CND   256
#define VN    4096
#define NPTS  32768
#define PB    4096
#define A_ELEMS (NPTS * CND)

#define MT      128                // points per CTA
#define TV      128                // codewords per V-tile
#define NVT     (VN / TV)          // 32
#define KCHUNK  32                 // k per staged W chunk
#define NCHUNK  (CND / KCHUNK)     // 8 chunks per V-tile
#define NSTAGES (NVT * NCHUNK)     // 256
#define THREADS 256
#define NB_VQ   (NPTS / MT)        // 256
#define NB_WR   128

// smem float offsets
#define SX_STRIDE 132
#define SW_STRIDE 36
#define OFF_SX    0                          // [256][132]
#define OFF_SW    (CND * SX_STRIDE)          // 2 x [128][36]
#define OFF_WSQ   (OFF_SW + 2 * TV * SW_STRIDE)
#define OFF_SCR   (OFF_WSQ + VN)             // [128][16] float
#define OFF_SID   (OFF_SCR + MT * 16)        // [128][16] int
#define SMEM_FLOATS (OFF_SID + MT * 16)
#define SMEM_BYTES  (SMEM_FLOATS * 4)        // 204800

__device__ float  g_wsq[VN];
__device__ int    g_cand[NPTS * 4];
__device__ int    g_idx[NPTS];
__device__ double g_blocksum[NB_WR];

__device__ __forceinline__ uint32_t f2tf32(float x) {
    uint32_t r;
    asm("cvt.rna.tf32.f32 %0, %1;" : "=r"(r) : "f"(x));
    return r;
}
__device__ __forceinline__ float tf32f(float x) { return __uint_as_float(f2tf32(x)); }

__device__ __forceinline__ void mma_tf32(float c[4],
                                         uint32_t a0, uint32_t a1, uint32_t a2, uint32_t a3,
                                         uint32_t b0, uint32_t b1) {
    asm volatile(
        "mma.sync.aligned.m16n8k8.row.col.f32.tf32.tf32.f32 "
        "{%0,%1,%2,%3}, {%4,%5,%6,%7}, {%8,%9}, {%0,%1,%2,%3};"
        : "+f"(c[0]), "+f"(c[1]), "+f"(c[2]), "+f"(c[3])
        : "r"(a0), "r"(a1), "r"(a2), "r"(a3), "r"(b0), "r"(b1));
}

// ---------------------------------------------------------------------------
// Kernel 0: ||w_v||^2 (exact fp32)
// ---------------------------------------------------------------------------
__global__ void wsq_kernel(const float* __restrict__ W) {
    int v = blockIdx.x * blockDim.x + threadIdx.x;
    if (v < VN) {
        const float* row = W + (size_t)v * CND;
        float s = 0.f;
        #pragma unroll 8
        for (int c = 0; c < CND; c++) s = fmaf(row[c], row[c], s);
        g_wsq[v] = s;
    }
}

// ---------------------------------------------------------------------------
// Kernel 1: TF32 mma.sync distance GEMM + exact-ish per-point approx top-4.
// 8 warps: wM = wid&1 (M half of 64), wN = wid>>1 (N quarter of 32).
// Per V-tile: mma accumulate -> per-thread slot(8 cols)-top-1 -> smem merge
// into per-point global approx top-4 (held by threads tid<128).
// ---------------------------------------------------------------------------
__global__ __launch_bounds__(THREADS, 1)
void vq_mma_kernel(const float* __restrict__ G, const float* __restrict__ W) {
    extern __shared__ float smem[];
    float* sx   = smem + OFF_SX;
    float* sw   = smem + OFF_SW;
    float* swsq = smem + OFF_WSQ;
    float* scr  = smem + OFF_SCR;
    int*   sid  = reinterpret_cast<int*>(smem + OFF_SID);

    const int tid  = threadIdx.x;
    const int wid  = tid >> 5;
    const int lane = tid & 31;
    const int ka   = lane & 3;     // k offset within fragment
    const int ra   = lane >> 2;    // row/col group
    const int wM   = wid & 1;
    const int wN   = wid >> 1;
    const int n0   = blockIdx.x * MT;
    const int b    = n0 / PB;
    const int p0   = n0 % PB;

    // Stage x tile: gmem [c][p] rows contiguous -> smem K-major [c][m], tf32.
    {
        const float* Gb = G + (size_t)b * CND * PB + p0;
        for (int i = tid; i < CND * (MT / 4); i += THREADS) {
            int c  = i >> 5;                   // MT/4 == 32
            int m4 = i & 31;
            float4 v = *reinterpret_cast<const float4*>(Gb + (size_t)c * PB + m4 * 4);
            float* d = sx + c * SX_STRIDE + m4 * 4;
            d[0] = tf32f(v.x); d[1] = tf32f(v.y); d[2] = tf32f(v.z); d[3] = tf32f(v.w);
        }
        for (int i = tid; i < VN; i += THREADS) swsq[i] = g_wsq[i];
    }

    // Stage W chunk s=0
    {
        int v = tid >> 1, half = tid & 1;
        const float4* src = reinterpret_cast<const float4*>(
            W + (size_t)v * CND + half * 16);
        float* dst = sw + v * SW_STRIDE + half * 16;
        #pragma unroll
        for (int j = 0; j < 4; j++) {
            float4 t = src[j];
            dst[4*j+0] = tf32f(t.x); dst[4*j+1] = tf32f(t.y);
            dst[4*j+2] = tf32f(t.z); dst[4*j+3] = tf32f(t.w);
        }
    }
    __syncthreads();

    float acc[4][4][4];
    #pragma unroll
    for (int mt = 0; mt < 4; mt++)
        #pragma unroll
        for (int nt = 0; nt < 4; nt++)
            #pragma unroll
            for (int i = 0; i < 4; i++) acc[mt][nt][i] = 0.f;

    // running per-point approx top-4 (valid in tid<128)
    float s0 = 3.4e38f, s1 = 3.4e38f, s2 = 3.4e38f, s3 = 3.4e38f;
    int   i0 = 0, i1 = 0, i2 = 0, i3 = 0;

    #pragma unroll 1
    for (int s = 0; s < NSTAGES; s++) {
        const int vt  = s >> 3;
        const int kc  = s & 7;
        const int cur = s & 1;

        // stage next W chunk into the other buffer
        if (s + 1 < NSTAGES) {
            const int vt1 = (s + 1) >> 3, kc1 = (s + 1) & 7;
            int v = tid >> 1, half = tid & 1;
            const float4* src = reinterpret_cast<const float4*>(
                W + (size_t)(vt1 * TV + v) * CND + kc1 * KCHUNK + half * 16);
            float* dst = sw + ((s + 1) & 1) * TV * SW_STRIDE + v * SW_STRIDE + half * 16;
            #pragma unroll
            for (int j = 0; j < 4; j++) {
                float4 t = src[j];
                dst[4*j+0] = tf32f(t.x); dst[4*j+1] = tf32f(t.y);
                dst[4*j+2] = tf32f(t.z); dst[4*j+3] = tf32f(t.w);
            }
        }

        // consume current chunk: 4 k8 steps x (4 m-tiles x 4 n-tiles) mma
        const float* swb = sw + cur * TV * SW_STRIDE;
        #pragma unroll
        for (int k8 = 0; k8 < 4; k8++) {
            const float* sxk = sx + (kc * KCHUNK + k8 * 8) * SX_STRIDE;
            uint32_t a[4][4];
            #pragma unroll
            for (int mt = 0; mt < 4; mt++) {
                const int m = wM * 64 + mt * 16 + ra;
                a[mt][0] = __float_as_uint(sxk[ka * SX_STRIDE + m]);
                a[mt][1] = __float_as_uint(sxk[ka * SX_STRIDE + m + 8]);
                a[mt][2] = __float_as_uint(sxk[(ka + 4) * SX_STRIDE + m]);
                a[mt][3] = __float_as_uint(sxk[(ka + 4) * SX_STRIDE + m + 8]);
            }
            uint32_t bb[4][2];
            #pragma unroll
            for (int nt = 0; nt < 4; nt++) {
                const int v = wN * 32 + nt * 8 + ra;
                bb[nt][0] = __float_as_uint(swb[v * SW_STRIDE + k8 * 8 + ka]);
                bb[nt][1] = __float_as_uint(swb[v * SW_STRIDE + k8 * 8 + ka + 4]);
            }
            #pragma unroll
            for (int mt = 0; mt < 4; mt++)
                #pragma unroll
                for (int nt = 0; nt < 4; nt++)
                    mma_tf32(acc[mt][nt], a[mt][0], a[mt][1], a[mt][2], a[mt][3],
                             bb[nt][0], bb[nt][1]);
        }

        // V-tile boundary: epilogue
        if (kc == 7) {
            // per-thread slot top-1 for its 8 rows over its 8 cols of this tile
            float tb[8]; int ti[8];
            #pragma unroll
            for (int r = 0; r < 8; r++) { tb[r] = 3.4e38f; ti[r] = 0; }
            #pragma unroll
            for (int mt = 0; mt < 4; mt++)
                #pragma unroll
                for (int nt = 0; nt < 4; nt++) {
                    const int cb = vt * TV + wN * 32 + nt * 8 + 2 * ka;
                    const float w0 = swsq[cb], w1 = swsq[cb + 1];
                    const float e00 = fmaf(-2.f, acc[mt][nt][0], w0);
                    const float e01 = fmaf(-2.f, acc[mt][nt][1], w1);
                    const float e10 = fmaf(-2.f, acc[mt][nt][2], w0);
                    const float e11 = fmaf(-2.f, acc[mt][nt][3], w1);
                    if (e00 < tb[2*mt])   { tb[2*mt]   = e00; ti[2*mt]   = cb;     }
                    if (e01 < tb[2*mt])   { tb[2*mt]   = e01; ti[2*mt]   = cb + 1; }
                    if (e10 < tb[2*mt+1]) { tb[2*mt+1] = e10; ti[2*mt+1] = cb;     }
                    if (e11 < tb[2*mt+1]) { tb[2*mt+1] = e11; ti[2*mt+1] = cb + 1; }
                    // reset acc for next tile
                    acc[mt][nt][0] = acc[mt][nt][1] = acc[mt][nt][2] = acc[mt][nt][3] = 0.f;
                }
            // publish slot winners: row r, slot = wN*4 + ka
            const int slot = wN * 4 + ka;
            #pragma unroll
            for (int mt = 0; mt < 4; mt++) {
                const int r0 = wM * 64 + mt * 16 + ra;
                scr[r0 * 16 + slot]       = tb[2*mt];
                sid[r0 * 16 + slot]       = ti[2*mt];
                scr[(r0 + 8) * 16 + slot] = tb[2*mt+1];
                sid[(r0 + 8) * 16 + slot] = ti[2*mt+1];
            }
            __syncthreads();
            // merge 16 slot winners into running per-point top-4
            if (tid < MT) {
                #pragma unroll
                for (int t = 0; t < 16; t++) {
                    const float sc = scr[tid * 16 + t];
                    const int   ii = sid[tid * 16 + t];
                    if (sc < s3) {
                        if (sc < s0)      { s3=s2;i3=i2; s2=s1;i2=i1; s1=s0;i1=i0; s0=sc;i0=ii; }
                        else if (sc < s1) { s3=s2;i3=i2; s2=s1;i2=i1; s1=sc;i1=ii; }
                        else if (sc < s2) { s3=s2;i3=i2; s2=sc;i2=ii; }
                        else              { s3=sc;i3=ii; }
                    }
                }
            }
        }
        __syncthreads();
    }

    if (tid < MT) {
        const int n = n0 + tid;
        g_cand[n * 4 + 0] = i0;
        g_cand[n * 4 + 1] = i1;
        g_cand[n * 4 + 2] = i2;
        g_cand[n * 4 + 3] = i3;
    }
}

// ---------------------------------------------------------------------------
// Kernel 2: exact fp32 rescore of 4 candidates -> final argmin (tie: min idx)
// ---------------------------------------------------------------------------
__global__ __launch_bounds__(256)
void rescore_kernel(const float* __restrict__ G, const float* __restrict__ W,
                    float* __restrict__ out_idx) {
    const int n = blockIdx.x * blockDim.x + threadIdx.x;
    const int b = n / PB, p = n % PB;
    const float* g = G + (size_t)b * CND * PB + p;

    int v[4];
    #pragma unroll
    for (int j = 0; j < 4; j++) v[j] = g_cand[n * 4 + j];

    float dot[4] = {0.f, 0.f, 0.f, 0.f};
    const float* w0 = W + (size_t)v[0] * CND;
    const float* w1 = W + (size_t)v[1] * CND;
    const float* w2 = W + (size_t)v[2] * CND;
    const float* w3 = W + (size_t)v[3] * CND;
    #pragma unroll 4
    for (int c = 0; c < CND; c++) {
        const float x = g[(size_t)c * PB];
        dot[0] = fmaf(x, __ldg(w0 + c), dot[0]);
        dot[1] = fmaf(x, __ldg(w1 + c), dot[1]);
        dot[2] = fmaf(x, __ldg(w2 + c), dot[2]);
        dot[3] = fmaf(x, __ldg(w3 + c), dot[3]);
    }

    float bs = 3.4e38f; int bi = 0x7fffffff;
    #pragma unroll
    for (int j = 0; j < 4; j++) {
        const float sc = g_wsq[v[j]] - 2.f * dot[j];
        if (sc < bs || (sc == bs && v[j] < bi)) { bs = sc; bi = v[j]; }
    }
    g_idx[n]   = bi;
    out_idx[n] = (float)bi;
}

// ---------------------------------------------------------------------------
// Kernel 3: scatter quant outputs + fp64 MSE partials
// ---------------------------------------------------------------------------
__global__ __launch_bounds__(256)
void write_kernel(const float* __restrict__ G, const float* __restrict__ W,
                  float* __restrict__ out) {
    const int n = blockIdx.x * blockDim.x + threadIdx.x;
    const int b = n / PB, p = n % PB;
    const int idx = g_idx[n];
    const float* wrow = W + (size_t)idx * CND;
    const float* g    = G + (size_t)b * CND * PB + p;
    float* q1 = out + (size_t)b * CND * PB + p;
    float* q2 = q1 + (size_t)A_ELEMS;

    double sum = 0.0;
    #pragma unroll 4
    for (int c = 0; c < CND; c++) {
        float w  = __ldg(wrow + c);
        float gg = g[(size_t)c * PB];
        q1[(size_t)c * PB] = w;
        q2[(size_t)c * PB] = w;
        float d = gg - w;
        sum += (double)d * (double)d;
    }

    __shared__ double sred[256];
    sred[threadIdx.x] = sum;
    __syncthreads();
    for (int st = 128; st > 0; st >>= 1) {
        if (threadIdx.x < st) sred[threadIdx.x] += sred[threadIdx.x + st];
        __syncthreads();
    }
    if (threadIdx.x == 0) g_blocksum[blockIdx.x] = sred[0];
}

__global__ void final_kernel(float* __restrict__ out) {
    double s = 0.0;
    for (int i = 0; i < NB_WR; i++) s += g_blocksum[i];
    out[2 * (size_t)A_ELEMS + NPTS] = (float)(s / ((double)NPTS * (double)CND));
}

// ---------------------------------------------------------------------------
// Launch
// ---------------------------------------------------------------------------
extern "C" void kernel_launch(void* const* d_in, const int* in_sizes, int n_in,
                              void* d_out, int out_size) {
    const float* G = (const float*)d_in[0];
    const float* W = (const float*)d_in[1];
    float* out = (float*)d_out;

    cudaFuncSetAttribute(vq_mma_kernel,
                         cudaFuncAttributeMaxDynamicSharedMemorySize, SMEM_BYTES);

    wsq_kernel<<<(VN + 255) / 256, 256>>>(W);
    vq_mma_kernel<<<NB_VQ, THREADS, SMEM_BYTES>>>(G, W);
    rescore_kernel<<<NPTS / 256, 256>>>(G, W, out + 2 * (size_t)A_ELEMS);
    write_kernel<<<NB_WR, 256>>>(G, W, out);
    final_kernel<<<1, 1>>>(out);
}

// round 6
// speedup vs baseline: 2.2474x; 1.4341x over previous
#include <cuda_runtime.h>
#include <cuda_bf16.h>
#include <cstdint>

#define CND   256
#define VN    4096
#define NPTS  32768
#define PB    4096
#define A_ELEMS (NPTS * CND)

#define MT      128                // points per CTA
#define TV      128                // codewords per V-tile
#define NVT     32
#define KCHUNK  32
#define NSTAGES 256                // NVT * 8
#define THREADS 256
#define NB_VQ   256
#define NB_FN   256                // finalize blocks (128 threads)
#define NCAND   6

// smem byte offsets
#define SXS 264                    // sx row stride in halves (conflict-free: 132 words -> 4*ra+ka)
#define SWS 40                     // sw row stride in halves (20 words -> 20*ra+ka distinct)
#define OFF_SX  0                  // 128*264*2 = 67584
#define OFF_SW  67584              // 2*128*40*2 = 20480
#define OFF_SCR 88064              // 128*16*4   = 8192
#define OFF_SID 96256              // 8192
#define SMEM_BYTES 104448          // fits 2 CTAs/SM

__device__ float  g_wsq[VN];
__device__ int    g_cand[NPTS * NCAND];
__device__ double g_blocksum[NB_FN];

__device__ __forceinline__ void mma_bf16(float c[4], const uint32_t a[4],
                                         const uint32_t b2[2]) {
    asm volatile(
        "mma.sync.aligned.m16n8k16.row.col.f32.bf16.bf16.f32 "
        "{%0,%1,%2,%3}, {%4,%5,%6,%7}, {%8,%9}, {%0,%1,%2,%3};"
        : "+f"(c[0]), "+f"(c[1]), "+f"(c[2]), "+f"(c[3])
        : "r"(a[0]), "r"(a[1]), "r"(a[2]), "r"(a[3]), "r"(b2[0]), "r"(b2[1]));
}

// ---------------------------------------------------------------------------
// Kernel 0: ||w_v||^2, one warp per row
// ---------------------------------------------------------------------------
__global__ __launch_bounds__(256)
void wsq_kernel(const float* __restrict__ W) {
    const int warp = (blockIdx.x * 8) + (threadIdx.x >> 5);
    const int lane = threadIdx.x & 31;
    const float4* row = reinterpret_cast<const float4*>(W + (size_t)warp * CND);
    float4 u = row[lane];
    float4 v = row[lane + 32];
    float s = u.x*u.x + u.y*u.y + u.z*u.z + u.w*u.w
            + v.x*v.x + v.y*v.y + v.z*v.z + v.w*v.w;
    #pragma unroll
    for (int o = 16; o > 0; o >>= 1) s += __shfl_down_sync(0xFFFFFFFF, s, o);
    if (lane == 0) g_wsq[warp] = s;
}

// ---------------------------------------------------------------------------
// Kernel 1: bf16 mma.sync distance GEMM; per-slot top-2 -> global top-6 filter
// ---------------------------------------------------------------------------
__device__ __forceinline__ void stage_w(const float* __restrict__ W,
                                        __nv_bfloat16* sw, int s, int tid) {
    const int vt = s >> 3, kc = s & 7;
    const int v = tid >> 1, h = tid & 1;
    const float4* src = reinterpret_cast<const float4*>(
        W + (size_t)(vt * TV + v) * CND + kc * KCHUNK + h * 16);
    __nv_bfloat16* dst = sw + (s & 1) * (TV * SWS) + v * SWS + h * 16;
    #pragma unroll
    for (int j = 0; j < 2; j++) {
        float4 t0 = src[2 * j], t1 = src[2 * j + 1];
        __nv_bfloat162 h0 = __floats2bfloat162_rn(t0.x, t0.y);
        __nv_bfloat162 h1 = __floats2bfloat162_rn(t0.z, t0.w);
        __nv_bfloat162 h2 = __floats2bfloat162_rn(t1.x, t1.y);
        __nv_bfloat162 h3 = __floats2bfloat162_rn(t1.z, t1.w);
        uint4 u;
        u.x = *reinterpret_cast<uint32_t*>(&h0);
        u.y = *reinterpret_cast<uint32_t*>(&h1);
        u.z = *reinterpret_cast<uint32_t*>(&h2);
        u.w = *reinterpret_cast<uint32_t*>(&h3);
        *reinterpret_cast<uint4*>(dst + j * 8) = u;
    }
}

__global__ __launch_bounds__(THREADS, 2)
void vq_mma_kernel(const float* __restrict__ G, const float* __restrict__ W) {
    extern __shared__ char smem[];
    __nv_bfloat16* sx  = reinterpret_cast<__nv_bfloat16*>(smem + OFF_SX);
    __nv_bfloat16* sw  = reinterpret_cast<__nv_bfloat16*>(smem + OFF_SW);
    float*         scr = reinterpret_cast<float*>(smem + OFF_SCR);
    int*           sid = reinterpret_cast<int*>(smem + OFF_SID);

    const int tid  = threadIdx.x;
    const int wid  = tid >> 5;
    const int lane = tid & 31;
    const int ka   = lane & 3;
    const int ra   = lane >> 2;
    const int wM   = wid & 1;
    const int wN   = wid >> 1;
    const int n0   = blockIdx.x * MT;
    const int b    = n0 / PB;
    const int p0   = n0 % PB;

    // Stage A: transpose G [c][p] -> sx [m][k] bf16 (coalesced gmem reads)
    {
        const float* Gb = G + (size_t)b * CND * PB + p0;
        const int p = tid & 127, ch = tid >> 7;
        __nv_bfloat16* dst = sx + p * SXS;
        #pragma unroll 4
        for (int c4 = 0; c4 < 32; c4++) {
            const int c = ch * 128 + c4 * 4;
            float x0 = Gb[(size_t)(c + 0) * PB + p];
            float x1 = Gb[(size_t)(c + 1) * PB + p];
            float x2 = Gb[(size_t)(c + 2) * PB + p];
            float x3 = Gb[(size_t)(c + 3) * PB + p];
            __nv_bfloat162 h01 = __floats2bfloat162_rn(x0, x1);
            __nv_bfloat162 h23 = __floats2bfloat162_rn(x2, x3);
            uint2 u;
            u.x = *reinterpret_cast<uint32_t*>(&h01);
            u.y = *reinterpret_cast<uint32_t*>(&h23);
            *reinterpret_cast<uint2*>(dst + c) = u;
        }
    }
    stage_w(W, sw, 0, tid);
    __syncthreads();

    float acc[4][4][4];
    #pragma unroll
    for (int mt = 0; mt < 4; mt++)
        #pragma unroll
        for (int nt = 0; nt < 4; nt++)
            #pragma unroll
            for (int i = 0; i < 4; i++) acc[mt][nt][i] = 0.f;

    float bs[NCAND]; int bi[NCAND];
    #pragma unroll
    for (int q = 0; q < NCAND; q++) { bs[q] = 3.4e38f; bi[q] = 0; }

    #pragma unroll 1
    for (int s = 0; s < NSTAGES; s++) {
        if (s + 1 < NSTAGES) stage_w(W, sw, s + 1, tid);

        const __nv_bfloat16* swb = sw + (s & 1) * (TV * SWS);
        const int kc = s & 7;
        #pragma unroll
        for (int kk = 0; kk < 2; kk++) {
            const int kb = kc * KCHUNK + kk * 16;
            uint32_t af[4][4];
            #pragma unroll
            for (int mt = 0; mt < 4; mt++) {
                const int m = wM * 64 + mt * 16 + ra;
                const __nv_bfloat16* r0 = sx + m * SXS + kb + 2 * ka;
                const __nv_bfloat16* r1 = r0 + 8 * SXS;
                af[mt][0] = *reinterpret_cast<const uint32_t*>(r0);
                af[mt][1] = *reinterpret_cast<const uint32_t*>(r1);
                af[mt][2] = *reinterpret_cast<const uint32_t*>(r0 + 8);
                af[mt][3] = *reinterpret_cast<const uint32_t*>(r1 + 8);
            }
            uint32_t bf[4][2];
            #pragma unroll
            for (int nt = 0; nt < 4; nt++) {
                const __nv_bfloat16* br =
                    swb + (wN * 32 + nt * 8 + ra) * SWS + kk * 16 + 2 * ka;
                bf[nt][0] = *reinterpret_cast<const uint32_t*>(br);
                bf[nt][1] = *reinterpret_cast<const uint32_t*>(br + 8);
            }
            #pragma unroll
            for (int mt = 0; mt < 4; mt++)
                #pragma unroll
                for (int nt = 0; nt < 4; nt++)
                    mma_bf16(acc[mt][nt], af[mt], bf[nt]);
        }

        if (kc == 7) {
            const int vt = s >> 3;
            // per-row top-2 among this thread's 8 cols of the tile
            float t1v[8], t2v[8]; int t1i[8], t2i[8];
            #pragma unroll
            for (int r = 0; r < 8; r++) { t1v[r] = 3.4e38f; t2v[r] = 3.4e38f; t1i[r] = 0; t2i[r] = 0; }
            #pragma unroll
            for (int nt = 0; nt < 4; nt++) {
                const int cb = vt * TV + wN * 32 + nt * 8 + 2 * ka;
                const float w0 = __ldg(&g_wsq[cb]);
                const float w1 = __ldg(&g_wsq[cb + 1]);
                #pragma unroll
                for (int mt = 0; mt < 4; mt++) {
                    const float e00 = fmaf(-2.f, acc[mt][nt][0], w0);
                    const float e01 = fmaf(-2.f, acc[mt][nt][1], w1);
                    const float e10 = fmaf(-2.f, acc[mt][nt][2], w0);
                    const float e11 = fmaf(-2.f, acc[mt][nt][3], w1);
                    acc[mt][nt][0] = acc[mt][nt][1] = acc[mt][nt][2] = acc[mt][nt][3] = 0.f;
                    #pragma unroll
                    for (int h = 0; h < 2; h++) {
                        const float ea = h ? e10 : e00;
                        const float eb = h ? e11 : e01;
                        const int   r  = 2 * mt + h;
                        if (ea < t2v[r]) {
                            if (ea < t1v[r]) { t2v[r]=t1v[r]; t2i[r]=t1i[r]; t1v[r]=ea; t1i[r]=cb; }
                            else             { t2v[r]=ea; t2i[r]=cb; }
                        }
                        if (eb < t2v[r]) {
                            if (eb < t1v[r]) { t2v[r]=t1v[r]; t2i[r]=t1i[r]; t1v[r]=eb; t1i[r]=cb+1; }
                            else             { t2v[r]=eb; t2i[r]=cb+1; }
                        }
                    }
                }
            }
            const int slot = wN * 4 + ka;
            // round 1: slot winners
            #pragma unroll
            for (int mt = 0; mt < 4; mt++) {
                const int r0 = wM * 64 + mt * 16 + ra;
                scr[r0 * 16 + slot]       = t1v[2*mt];   sid[r0 * 16 + slot]       = t1i[2*mt];
                scr[(r0 + 8) * 16 + slot] = t1v[2*mt+1]; sid[(r0 + 8) * 16 + slot] = t1i[2*mt+1];
            }
            __syncthreads();
            if (tid < MT) {
                #pragma unroll
                for (int t = 0; t < 16; t++) {
                    float cs = scr[tid * 16 + t]; int ci = sid[tid * 16 + t];
                    if (cs < bs[NCAND - 1]) {
                        #pragma unroll
                        for (int q = 0; q < NCAND; q++)
                            if (cs < bs[q]) {
                                float ts = bs[q]; int ti = bi[q];
                                bs[q] = cs; bi[q] = ci; cs = ts; ci = ti;
                            }
                    }
                }
            }
            __syncthreads();
            // round 2: slot runners-up
            #pragma unroll
            for (int mt = 0; mt < 4; mt++) {
                const int r0 = wM * 64 + mt * 16 + ra;
                scr[r0 * 16 + slot]       = t2v[2*mt];   sid[r0 * 16 + slot]       = t2i[2*mt];
                scr[(r0 + 8) * 16 + slot] = t2v[2*mt+1]; sid[(r0 + 8) * 16 + slot] = t2i[2*mt+1];
            }
            __syncthreads();
            if (tid < MT) {
                #pragma unroll
                for (int t = 0; t < 16; t++) {
                    float cs = scr[tid * 16 + t]; int ci = sid[tid * 16 + t];
                    if (cs < bs[NCAND - 1]) {
                        #pragma unroll
                        for (int q = 0; q < NCAND; q++)
                            if (cs < bs[q]) {
                                float ts = bs[q]; int ti = bi[q];
                                bs[q] = cs; bi[q] = ci; cs = ts; ci = ti;
                            }
                    }
                }
            }
        }
        __syncthreads();
    }

    if (tid < MT) {
        const int n = n0 + tid;
        #pragma unroll
        for (int q = 0; q < NCAND; q++) g_cand[n * NCAND + q] = bi[q];
    }
}

// ---------------------------------------------------------------------------
// Kernel 2 (fused): exact fp32 rescore of 6 candidates -> argmin, scatter
// quant outputs, per-point MSE via  gsq - 2*dot + wsq  (fp64 combine)
// ---------------------------------------------------------------------------
__global__ __launch_bounds__(128)
void finalize_kernel(const float* __restrict__ G, const float* __restrict__ W,
                     float* __restrict__ out) {
    const int n = blockIdx.x * 128 + threadIdx.x;
    const int b = n / PB, p = n % PB;
    const float* g = G + (size_t)b * CND * PB + p;

    int v[NCAND];
    #pragma unroll
    for (int j = 0; j < NCAND; j++) v[j] = g_cand[n * NCAND + j];

    const float* wr0 = W + (size_t)v[0] * CND;
    const float* wr1 = W + (size_t)v[1] * CND;
    const float* wr2 = W + (size_t)v[2] * CND;
    const float* wr3 = W + (size_t)v[3] * CND;
    const float* wr4 = W + (size_t)v[4] * CND;
    const float* wr5 = W + (size_t)v[5] * CND;

    float dot[NCAND] = {0.f, 0.f, 0.f, 0.f, 0.f, 0.f};
    float gsq = 0.f;
    #pragma unroll 4
    for (int c = 0; c < CND; c++) {
        const float x = g[(size_t)c * PB];
        gsq    = fmaf(x, x, gsq);
        dot[0] = fmaf(x, __ldg(wr0 + c), dot[0]);
        dot[1] = fmaf(x, __ldg(wr1 + c), dot[1]);
        dot[2] = fmaf(x, __ldg(wr2 + c), dot[2]);
        dot[3] = fmaf(x, __ldg(wr3 + c), dot[3]);
        dot[4] = fmaf(x, __ldg(wr4 + c), dot[4]);
        dot[5] = fmaf(x, __ldg(wr5 + c), dot[5]);
    }

    float bsx = 3.4e38f; int bix = 0x7fffffff; float bdot = 0.f, bwsq = 0.f;
    #pragma unroll
    for (int j = 0; j < NCAND; j++) {
        const float ws = g_wsq[v[j]];
        const float sc = ws - 2.f * dot[j];
        if (sc < bsx || (sc == bsx && v[j] < bix)) {
            bsx = sc; bix = v[j]; bdot = dot[j]; bwsq = ws;
        }
    }

    out[2 * (size_t)A_ELEMS + n] = (float)bix;

    const float* wbest = W + (size_t)bix * CND;
    float* q1 = out + (size_t)b * CND * PB + p;
    float* q2 = q1 + (size_t)A_ELEMS;
    #pragma unroll 4
    for (int c = 0; c < CND; c++) {
        const float w = __ldg(wbest + c);
        q1[(size_t)c * PB] = w;
        q2[(size_t)c * PB] = w;
    }

    const double d2 = (double)gsq - 2.0 * (double)bdot + (double)bwsq;

    __shared__ double sred[128];
    sred[threadIdx.x] = d2;
    __syncthreads();
    for (int st = 64; st > 0; st >>= 1) {
        if (threadIdx.x < st) sred[threadIdx.x] += sred[threadIdx.x + st];
        __syncthreads();
    }
    if (threadIdx.x == 0) g_blocksum[blockIdx.x] = sred[0];
}

__global__ void final_kernel(float* __restrict__ out) {
    double s = 0.0;
    for (int i = 0; i < NB_FN; i++) s += g_blocksum[i];
    out[2 * (size_t)A_ELEMS + NPTS] = (float)(s / ((double)NPTS * (double)CND));
}

// ---------------------------------------------------------------------------
// Launch
// ---------------------------------------------------------------------------
extern "C" void kernel_launch(void* const* d_in, const int* in_sizes, int n_in,
                              void* d_out, int out_size) {
    const float* G = (const float*)d_in[0];
    const float* W = (const float*)d_in[1];
    float* out = (float*)d_out;

    cudaFuncSetAttribute(vq_mma_kernel,
                         cudaFuncAttributeMaxDynamicSharedMemorySize, SMEM_BYTES);

    wsq_kernel<<<VN / 8, 256>>>(W);
    vq_mma_kernel<<<NB_VQ, THREADS, SMEM_BYTES>>>(G, W);
    finalize_kernel<<<NB_FN, 128>>>(G, W, out);
    final_kernel<<<1, 1>>>(out);
}